// round 5
// baseline (speedup 1.0000x reference)
#include <cuda_runtime.h>

#define Tn   2048
#define Bn   512
#define INn  27
#define Hn   64
#define OUTn 26
#define Gn   256   // 4*H

// 256 MB scratch for h_new[t][b][h] (allowed: __device__ global, no cudaMalloc)
__device__ float g_hall[Tn * Bn * Hn];

// ---- packed f32x2 helpers (Blackwell FFMA2) ----
__device__ __forceinline__ unsigned long long pack2(float lo, float hi) {
    unsigned long long r;
    asm("mov.b64 %0, {%1, %2};" : "=l"(r) : "f"(lo), "f"(hi));
    return r;
}
__device__ __forceinline__ void unpack2(unsigned long long v, float& lo, float& hi) {
    asm("mov.b64 {%0, %1}, %2;" : "=f"(lo), "=f"(hi) : "l"(v));
}
__device__ __forceinline__ unsigned long long ffma2(unsigned long long a,
                                                    unsigned long long b,
                                                    unsigned long long c) {
    unsigned long long d;
    asm("fma.rn.f32x2 %0, %1, %2, %3;" : "=l"(d) : "l"(a), "l"(b), "l"(c));
    return d;
}

__device__ __forceinline__ float fast_sigmoid(float x) {
    // 1/(1+exp(-x)); robust at extremes (exp->inf => 0, exp->0 => 1)
    return __fdividef(1.0f, 1.0f + __expf(-x));
}
__device__ __forceinline__ float fast_tanh(float x) {
    // 1 - 2/(exp(2x)+1); robust at extremes
    float e = __expf(2.0f * x);
    return 1.0f - __fdividef(2.0f, e + 1.0f);
}

// ============================================================================
// Stage 1: 512 independent LSTMs. One CTA per batch element, one gate per
// thread, weights register-resident, h broadcast from SMEM.
// ============================================================================
__global__ __launch_bounds__(256)
void lstm_kernel(const float* __restrict__ x,      // [T,B,IN]
                 const float* __restrict__ W_ih,   // [256,27]
                 const float* __restrict__ W_hh,   // [256,64]
                 const float* __restrict__ b_ih,   // [256]
                 const float* __restrict__ b_hh)   // [256]
{
    const int b = blockIdx.x;      // batch element
    const int g = threadIdx.x;     // gate id 0..255

    __shared__ float h_s[Hn];           // current hidden state (8B aligned)
    __shared__ float gates_s[Gn];       // activated gates
    __shared__ float x_s[2][28];        // double-buffered x_t (padded to 28)

    // ---- load this gate's weights into registers, packed as f32x2 ----
    unsigned long long whh[32];         // 64 W_hh values
    unsigned long long wih[14];         // 27 W_ih values (+1 zero pad)
    {
        const float* wr = W_hh + g * Hn;
#pragma unroll
        for (int k = 0; k < 32; k++) whh[k] = pack2(wr[2*k], wr[2*k+1]);
        const float* wr2 = W_ih + g * INn;
#pragma unroll
        for (int k = 0; k < 14; k++) {
            float lo = wr2[2*k];
            float hi = (2*k + 1 < INn) ? wr2[2*k+1] : 0.0f;
            wih[k] = pack2(lo, hi);
        }
    }
    const float bias  = b_ih[g] + b_hh[g];
    const int   gtype = g >> 6;   // 0:i  1:f  2:g(tanh)  3:o

    float c_reg = 0.0f;           // cell state, owned by threads 0..63

    // ---- init shared state ----
    if (g < Hn)  h_s[g] = 0.0f;
    if (g == 0) { x_s[0][27] = 0.0f; x_s[1][27] = 0.0f; }
    if (g < INn) x_s[0][g] = x[b * INn + g];   // t = 0
    __syncthreads();

    int buf = 0;
    for (int t = 0; t < Tn; t++) {
        // prefetch x for t+1 early (LDG latency hidden behind gate compute)
        float xr = 0.0f;
        if (g >= 64 && g < 64 + INn && (t + 1) < Tn)
            xr = x[((t + 1) * Bn + b) * INn + (g - 64)];

        // ---- gate pre-activation: h.W_hh + x.W_ih (packed f32x2 FMAs) ----
        unsigned long long a0 = 0ull, a1 = 0ull;  // {0.f,0.f}
        const unsigned long long* hp = (const unsigned long long*)h_s;
#pragma unroll
        for (int k = 0; k < 32; k += 2) {
            a0 = ffma2(hp[k],     whh[k],     a0);
            a1 = ffma2(hp[k + 1], whh[k + 1], a1);
        }
        const unsigned long long* xp = (const unsigned long long*)x_s[buf];
#pragma unroll
        for (int k = 0; k < 14; k += 2) {
            a0 = ffma2(xp[k],     wih[k],     a0);
            a1 = ffma2(xp[k + 1], wih[k + 1], a1);
        }
        float l0, h0, l1, h1;
        unpack2(a0, l0, h0);
        unpack2(a1, l1, h1);
        float acc = bias + ((l0 + h0) + (l1 + h1));

        float act = (gtype == 2) ? fast_tanh(acc) : fast_sigmoid(acc);
        gates_s[g] = act;
        __syncthreads();

        // ---- cell/hidden update (threads 0..63) + x stage-in (64..90) ----
        if (g < Hn) {
            float iv = gates_s[g];
            float fv = gates_s[Hn + g];
            float gv = gates_s[2 * Hn + g];
            float ov = gates_s[3 * Hn + g];
            c_reg = fv * c_reg + iv * gv;
            float hv = ov * fast_tanh(c_reg);
            h_s[g] = hv;
            g_hall[(t * Bn + b) * Hn + g] = hv;
        } else if (g < 64 + INn) {
            x_s[buf ^ 1][g - 64] = xr;
        }
        __syncthreads();
        buf ^= 1;
    }
}

// ============================================================================
// Stage 2: per-timestep BatchNorm (batch stats) -> LockedDropout -> max over
// batch -> FC with prev_guess concat. One CTA per timestep.
// ============================================================================
__global__ __launch_bounds__(256)
void bn_pool_fc_kernel(const float* __restrict__ pg,     // [T,OUT]
                       const float* __restrict__ gamma,  // [H]
                       const float* __restrict__ beta,   // [H]
                       const float* __restrict__ W_fc,   // [OUT, H+OUT]
                       const float* __restrict__ b_fc,   // [OUT]
                       const float* __restrict__ mask,   // [B,H]
                       float* __restrict__ out)          // [T,1,OUT]
{
    const int t   = blockIdx.x;
    const int tid = threadIdx.x;
    const int h   = tid & 63;
    const int grp = tid >> 6;     // 4 groups over batch

    const float* base = g_hall + (size_t)t * Bn * Hn;

    __shared__ float redA[4][Hn];
    __shared__ float redB[4][Hn];
    __shared__ float scale_s[Hn], shift_s[Hn];
    __shared__ float pooled[Hn];

    // pass 1: sum / sumsq over batch
    float s = 0.0f, ss = 0.0f;
    for (int bb = grp; bb < Bn; bb += 4) {
        float v = base[bb * Hn + h];
        s += v;
        ss += v * v;
    }
    redA[grp][h] = s;
    redB[grp][h] = ss;
    __syncthreads();

    if (tid < Hn) {
        float sum = redA[0][tid] + redA[1][tid] + redA[2][tid] + redA[3][tid];
        float sq  = redB[0][tid] + redB[1][tid] + redB[2][tid] + redB[3][tid];
        float mean = sum * (1.0f / Bn);
        float var  = sq * (1.0f / Bn) - mean * mean;
        float rstd = rsqrtf(var + 1e-5f);
        float sc   = rstd * gamma[tid];
        scale_s[tid] = sc;
        shift_s[tid] = beta[tid] - mean * sc;
    }
    __syncthreads();

    // pass 2: masked affine + max over batch
    float sc = scale_s[h], sh = shift_s[h];
    float mx = -3.402823466e38f;
    for (int bb = grp; bb < Bn; bb += 4) {
        float v  = base[bb * Hn + h];
        float hd = (v * sc + sh) * mask[bb * Hn + h];
        mx = fmaxf(mx, hd);
    }
    redA[grp][h] = mx;
    __syncthreads();

    if (tid < Hn)
        pooled[tid] = fmaxf(fmaxf(redA[0][tid], redA[1][tid]),
                            fmaxf(redA[2][tid], redA[3][tid]));
    __syncthreads();

    // FC: y[t][o] = [pooled, pg_t] . W_fc[o] + b_fc[o]
    if (tid < OUTn) {
        const float* w = W_fc + tid * (Hn + OUTn);
        float acc = b_fc[tid];
#pragma unroll
        for (int k = 0; k < Hn; k++) acc += pooled[k] * w[k];
#pragma unroll
        for (int k = 0; k < OUTn; k++) acc += pg[t * OUTn + k] * w[Hn + k];
        out[t * OUTn + tid] = acc;
    }
}

// ============================================================================
// Launch
// ============================================================================
extern "C" void kernel_launch(void* const* d_in, const int* in_sizes, int n_in,
                              void* d_out, int out_size) {
    const float* x      = (const float*)d_in[0];   // obscure_word [T,B,IN]
    const float* pg     = (const float*)d_in[1];   // prev_guess   [T,OUT]
    const float* W_ih   = (const float*)d_in[2];   // [4H,IN]
    const float* W_hh   = (const float*)d_in[3];   // [4H,H]
    const float* b_ih   = (const float*)d_in[4];   // [4H]
    const float* b_hh   = (const float*)d_in[5];   // [4H]
    const float* gamma  = (const float*)d_in[6];   // [H]
    const float* beta   = (const float*)d_in[7];   // [H]
    const float* W_fc   = (const float*)d_in[8];   // [OUT,H+OUT]
    const float* b_fc   = (const float*)d_in[9];   // [OUT]
    const float* dmask  = (const float*)d_in[10];  // [B,H]
    float* out = (float*)d_out;

    lstm_kernel<<<Bn, 256>>>(x, W_ih, W_hh, b_ih, b_hh);
    bn_pool_fc_kernel<<<Tn, 256>>>(pg, gamma, beta, W_fc, b_fc, dmask, out);
}